// round 8
// baseline (speedup 1.0000x reference)
#include <cuda_runtime.h>
#include <cuda_fp16.h>

// Problem constants (fixed by the reference: B=4, N=1024, FMAP=64, HID=32)
#define BB 4
#define NN 1024
#define FM 64
#define HID 32
#define ROWS (BB * NN)        // 4096
#define I_CHUNK 16
#define JT 128                // j-tile / block size for pair_kernel

// Precomputed projections, packed as half2 (h pairs). 4096 rows x 16 half2.
__device__ __align__(16) __half2 g_A[ROWS * 16];  // A' = X@W1a + b1
__device__ __align__(16) __half2 g_C[ROWS * 16];  // C  = X@W1b
__device__ __align__(16) __half2 g_w2h[16];       // W2/2 packed as half2
__device__ float g_bias2;                         // b2/2

// ---------------------------------------------------------------------------
// Stage 1: per-row projections. 512 blocks x 8 warps, 1 row/warp (max fill).
// Block 0 additionally packs W2/2 and b2/2.
// ---------------------------------------------------------------------------
__global__ __launch_bounds__(256) void prep_kernel(
    const float* __restrict__ X,    // [ROWS, 64]
    const float* __restrict__ W1,   // [128, 32]
    const float* __restrict__ b1,   // [32]
    const float* __restrict__ W2,   // [32]
    const float* __restrict__ b2)   // [1]
{
    __shared__ float sW1[2 * FM * HID];   // 16 KB
    __shared__ float sX[8][FM];

    const int tid = threadIdx.x;
    for (int idx = tid; idx < 2 * FM * HID; idx += 256) sW1[idx] = W1[idx];

    if (blockIdx.x == 0) {
        if (tid < 16) g_w2h[tid] = __floats2half2_rn(0.5f * W2[2 * tid],
                                                     0.5f * W2[2 * tid + 1]);
        if (tid == 16) g_bias2 = 0.5f * b2[0];
    }

    const int warp = tid >> 5;
    const int lane = tid & 31;
    const int row  = blockIdx.x * 8 + warp;

    sX[warp][lane]      = X[row * FM + lane];
    sX[warp][lane + 32] = X[row * FM + lane + 32];
    const float bias = b1[lane];
    __syncthreads();

    float a = bias;   // fold b1 into A'
    float c = 0.0f;
    #pragma unroll
    for (int k = 0; k < FM; k++) {
        float xk = sX[warp][k];                  // smem broadcast
        a = fmaf(xk, sW1[k * HID + lane], a);
        c = fmaf(xk, sW1[(k + FM) * HID + lane], c);
    }
    reinterpret_cast<__half*>(g_A)[row * HID + lane] = __float2half_rn(a);
    reinterpret_cast<__half*>(g_C)[row * HID + lane] = __float2half_rn(c);
}

// ---------------------------------------------------------------------------
// Stage 2: pairwise tanh + dot + sigmoid.
// grid = (N/JT, N/I_CHUNK, B) = (8, 64, 4) = 2048 blocks; block = 128 threads.
// Thread t owns j = jtile*128 + t, loops over I_CHUNK i's (2 at a time).
// ---------------------------------------------------------------------------
__device__ __forceinline__ __half2 tanh2_approx(__half2 x) {
    unsigned xi = *reinterpret_cast<unsigned*>(&x);
    unsigned ri;
    asm("tanh.approx.f16x2 %0, %1;" : "=r"(ri) : "r"(xi));
    return *reinterpret_cast<__half2*>(&ri);
}

__device__ __forceinline__ float tanhf_approx(float x) {
    float r;
    asm("tanh.approx.f32 %0, %1;" : "=f"(r) : "f"(x));
    return r;
}

__global__ __launch_bounds__(JT, 8) void pair_kernel(float* __restrict__ out)
{
    __shared__ __align__(16) __half2 sC[I_CHUNK * 16];

    const int b  = blockIdx.z;
    const int j  = blockIdx.x * JT + threadIdx.x;
    const int i0 = blockIdx.y * I_CHUNK;
    const int t  = threadIdx.x;

    // C tile (I_CHUNK rows x 16 half2 = 1 KB) into smem, vectorized.
    if (t < (I_CHUNK * 16) / 4) {
        reinterpret_cast<float4*>(sC)[t] =
            reinterpret_cast<const float4*>(g_C + ((size_t)b * NN + i0) * 16)[t];
    }

    // Per-thread A' row (register-resident) while the smem load is in flight.
    float4 av[4];
    const float4* gA = reinterpret_cast<const float4*>(g_A + ((size_t)b * NN + j) * 16);
    #pragma unroll
    for (int q = 0; q < 4; q++) av[q] = gA[q];
    const __half2* Aj = reinterpret_cast<const __half2*>(av);

    // W2/2 as half2, prepacked by prep_kernel: 2x LDG.128 (L2 broadcast).
    float4 wv[2];
    wv[0] = reinterpret_cast<const float4*>(g_w2h)[0];
    wv[1] = reinterpret_cast<const float4*>(g_w2h)[1];
    const __half2* w2h = reinterpret_cast<const __half2*>(wv);
    // NOTE: 8 half2 in wv cover w2h[0..7]; need 16 -> load 4 float4 total.
    float4 wv2[2];
    wv2[0] = reinterpret_cast<const float4*>(g_w2h)[2];
    wv2[1] = reinterpret_cast<const float4*>(g_w2h)[3];
    const __half2* w2h_hi = reinterpret_cast<const __half2*>(wv2);

    // Bias folded into accumulator init (exact to one rounding).
    const __half2 binit = __halves2half2(__float2half_rn(g_bias2),
                                         __ushort_as_half((unsigned short)0));
    const __half2 hzero = __float2half2_rn(0.0f);

    __syncthreads();

    float* outp = out + (size_t)b * NN * NN + (size_t)i0 * NN + j;

    #pragma unroll
    for (int ii = 0; ii < I_CHUNK; ii += 2) {
        const float4* crow0 = reinterpret_cast<const float4*>(sC + ii * 16);
        const float4* crow1 = reinterpret_cast<const float4*>(sC + (ii + 1) * 16);

        // Two independent accumulation chains (i and i+1).
        __half2 a0 = binit, a1 = hzero, a2 = hzero, a3 = hzero;   // i
        __half2 b0 = binit, b1v = hzero, b2v = hzero, b3 = hzero; // i+1

        #pragma unroll
        for (int q = 0; q < 4; q++) {
            const __half2* wq = (q < 2) ? (w2h + 4 * q) : (w2h_hi + 4 * (q - 2));
            float4 cv0 = crow0[q];                      // broadcast LDS.128
            float4 cv1 = crow1[q];
            const __half2* c0 = reinterpret_cast<const __half2*>(&cv0);
            const __half2* c1 = reinterpret_cast<const __half2*>(&cv1);

            __half2 t00 = tanh2_approx(__hadd2(Aj[4 * q + 0], c0[0]));
            __half2 t10 = tanh2_approx(__hadd2(Aj[4 * q + 0], c1[0]));
            __half2 t01 = tanh2_approx(__hadd2(Aj[4 * q + 1], c0[1]));
            __half2 t11 = tanh2_approx(__hadd2(Aj[4 * q + 1], c1[1]));
            __half2 t02 = tanh2_approx(__hadd2(Aj[4 * q + 2], c0[2]));
            __half2 t12 = tanh2_approx(__hadd2(Aj[4 * q + 2], c1[2]));
            __half2 t03 = tanh2_approx(__hadd2(Aj[4 * q + 3], c0[3]));
            __half2 t13 = tanh2_approx(__hadd2(Aj[4 * q + 3], c1[3]));

            a0  = __hfma2(t00, wq[0], a0);
            b0  = __hfma2(t10, wq[0], b0);
            a1  = __hfma2(t01, wq[1], a1);
            b1v = __hfma2(t11, wq[1], b1v);
            a2  = __hfma2(t02, wq[2], a2);
            b2v = __hfma2(t12, wq[2], b2v);
            a3  = __hfma2(t03, wq[3], a3);
            b3  = __hfma2(t13, wq[3], b3);
        }

        // Lean epilogue per i: 3 HADD2 + 1 HADD + 1 cvt + MUFU + FFMA + STG.
        __half2 sa = __hadd2(__hadd2(a0, a1), __hadd2(a2, a3));
        __half2 sb = __hadd2(__hadd2(b0, b1v), __hadd2(b2v, b3));
        float hla = __half2float(__hadd(__low2half(sa), __high2half(sa)));
        float hlb = __half2float(__hadd(__low2half(sb), __high2half(sb)));

        outp[(size_t)ii * NN]       = fmaf(0.5f, tanhf_approx(hla), 0.5f);
        outp[(size_t)(ii + 1) * NN] = fmaf(0.5f, tanhf_approx(hlb), 0.5f);
    }
}

// ---------------------------------------------------------------------------
// Launch: two graph-capturable kernel launches, no allocations, no syncs.
// Inputs (metadata order): X, W1, b1, W2, b2. Output: float32 [4,1024,1024].
// ---------------------------------------------------------------------------
extern "C" void kernel_launch(void* const* d_in, const int* in_sizes, int n_in,
                              void* d_out, int out_size)
{
    const float* X  = (const float*)d_in[0];
    const float* W1 = (const float*)d_in[1];
    const float* b1 = (const float*)d_in[2];
    const float* W2 = (const float*)d_in[3];
    const float* b2 = (const float*)d_in[4];
    float* out = (float*)d_out;

    prep_kernel<<<ROWS / 8, 256>>>(X, W1, b1, W2, b2);

    dim3 grid(NN / JT, NN / I_CHUNK, BB);   // (8, 64, 4) = 2048 blocks
    pair_kernel<<<grid, JT>>>(out);
}

// round 9
// speedup vs baseline: 1.0021x; 1.0021x over previous
#include <cuda_runtime.h>
#include <cuda_fp16.h>

// Problem constants (fixed by the reference: B=4, N=1024, FMAP=64, HID=32)
#define BB 4
#define NN 1024
#define FM 64
#define HID 32
#define ROWS (BB * NN)        // 4096
#define I_CHUNK 32            // -> 1024 blocks = exactly one wave (8/SM resident)
#define JT 128                // j-tile / block size for pair_kernel

// Precomputed projections, packed as half2 (h pairs). 4096 rows x 16 half2.
__device__ __align__(16) __half2 g_A[ROWS * 16];  // A' = X@W1a + b1
__device__ __align__(16) __half2 g_C[ROWS * 16];  // C  = X@W1b
__device__ __align__(16) __half2 g_w2h[16];       // W2/2 packed as half2
__device__ float g_bias2;                         // b2/2

// ---------------------------------------------------------------------------
// Stage 1: per-row projections. 512 blocks x 8 warps, 1 row/warp (max fill).
// Block 0 additionally packs W2/2 and b2/2.
// ---------------------------------------------------------------------------
__global__ __launch_bounds__(256) void prep_kernel(
    const float* __restrict__ X,    // [ROWS, 64]
    const float* __restrict__ W1,   // [128, 32]
    const float* __restrict__ b1,   // [32]
    const float* __restrict__ W2,   // [32]
    const float* __restrict__ b2)   // [1]
{
    __shared__ float sW1[2 * FM * HID];   // 16 KB
    __shared__ float sX[8][FM];

    const int tid = threadIdx.x;
    for (int idx = tid; idx < 2 * FM * HID; idx += 256) sW1[idx] = W1[idx];

    if (blockIdx.x == 0) {
        if (tid < 16) g_w2h[tid] = __floats2half2_rn(0.5f * W2[2 * tid],
                                                     0.5f * W2[2 * tid + 1]);
        if (tid == 16) g_bias2 = 0.5f * b2[0];
    }

    const int warp = tid >> 5;
    const int lane = tid & 31;
    const int row  = blockIdx.x * 8 + warp;

    sX[warp][lane]      = X[row * FM + lane];
    sX[warp][lane + 32] = X[row * FM + lane + 32];
    const float bias = b1[lane];
    __syncthreads();

    float a = bias;   // fold b1 into A'
    float c = 0.0f;
    #pragma unroll
    for (int k = 0; k < FM; k++) {
        float xk = sX[warp][k];                  // smem broadcast
        a = fmaf(xk, sW1[k * HID + lane], a);
        c = fmaf(xk, sW1[(k + FM) * HID + lane], c);
    }
    reinterpret_cast<__half*>(g_A)[row * HID + lane] = __float2half_rn(a);
    reinterpret_cast<__half*>(g_C)[row * HID + lane] = __float2half_rn(c);
}

// ---------------------------------------------------------------------------
// Stage 2: pairwise tanh + dot + sigmoid.
// grid = (N/JT, N/I_CHUNK, B) = (8, 32, 4) = 1024 blocks; block = 128 threads.
// Single wave: ~6.9 blocks/SM, 8 resident at 64 regs -> no mid-kernel churn.
// ---------------------------------------------------------------------------
__device__ __forceinline__ __half2 tanh2_approx(__half2 x) {
    unsigned xi = *reinterpret_cast<unsigned*>(&x);
    unsigned ri;
    asm("tanh.approx.f16x2 %0, %1;" : "=r"(ri) : "r"(xi));
    return *reinterpret_cast<__half2*>(&ri);
}

__device__ __forceinline__ float tanhf_approx(float x) {
    float r;
    asm("tanh.approx.f32 %0, %1;" : "=f"(r) : "f"(x));
    return r;
}

__global__ __launch_bounds__(JT, 8) void pair_kernel(float* __restrict__ out)
{
    __shared__ __align__(16) __half2 sC[I_CHUNK * 16];   // 2 KB

    const int b  = blockIdx.z;
    const int j  = blockIdx.x * JT + threadIdx.x;
    const int i0 = blockIdx.y * I_CHUNK;
    const int t  = threadIdx.x;

    // C tile (I_CHUNK rows x 16 half2): 128 float4 = one per thread.
    reinterpret_cast<float4*>(sC)[t] =
        reinterpret_cast<const float4*>(g_C + ((size_t)b * NN + i0) * 16)[t];

    // Per-thread A' row (register-resident) while the smem load is in flight.
    float4 av[4];
    const float4* gA = reinterpret_cast<const float4*>(g_A + ((size_t)b * NN + j) * 16);
    #pragma unroll
    for (int q = 0; q < 4; q++) av[q] = gA[q];
    const __half2* Aj = reinterpret_cast<const __half2*>(av);

    // W2/2 as half2, prepacked by prep_kernel: 4x LDG.128 (L2 broadcast).
    float4 wv[4];
    #pragma unroll
    for (int q = 0; q < 4; q++) wv[q] = reinterpret_cast<const float4*>(g_w2h)[q];
    const __half2* w2h = reinterpret_cast<const __half2*>(wv);

    // Bias folded into accumulator init (exact to one rounding).
    const __half2 binit = __halves2half2(__float2half_rn(g_bias2),
                                         __ushort_as_half((unsigned short)0));
    const __half2 hzero = __float2half2_rn(0.0f);

    __syncthreads();

    float* outp = out + (size_t)b * NN * NN + (size_t)i0 * NN + j;

    #pragma unroll 4
    for (int ii = 0; ii < I_CHUNK; ii += 2) {
        const float4* crow0 = reinterpret_cast<const float4*>(sC + ii * 16);
        const float4* crow1 = reinterpret_cast<const float4*>(sC + (ii + 1) * 16);

        // Two independent accumulation chains (i and i+1).
        __half2 a0 = binit, a1 = hzero, a2 = hzero, a3 = hzero;   // i
        __half2 b0 = binit, b1v = hzero, b2v = hzero, b3 = hzero; // i+1

        #pragma unroll
        for (int q = 0; q < 4; q++) {
            float4 cv0 = crow0[q];                      // broadcast LDS.128
            float4 cv1 = crow1[q];
            const __half2* c0 = reinterpret_cast<const __half2*>(&cv0);
            const __half2* c1 = reinterpret_cast<const __half2*>(&cv1);

            __half2 t00 = tanh2_approx(__hadd2(Aj[4 * q + 0], c0[0]));
            __half2 t10 = tanh2_approx(__hadd2(Aj[4 * q + 0], c1[0]));
            __half2 t01 = tanh2_approx(__hadd2(Aj[4 * q + 1], c0[1]));
            __half2 t11 = tanh2_approx(__hadd2(Aj[4 * q + 1], c1[1]));
            __half2 t02 = tanh2_approx(__hadd2(Aj[4 * q + 2], c0[2]));
            __half2 t12 = tanh2_approx(__hadd2(Aj[4 * q + 2], c1[2]));
            __half2 t03 = tanh2_approx(__hadd2(Aj[4 * q + 3], c0[3]));
            __half2 t13 = tanh2_approx(__hadd2(Aj[4 * q + 3], c1[3]));

            a0  = __hfma2(t00, w2h[4 * q + 0], a0);
            b0  = __hfma2(t10, w2h[4 * q + 0], b0);
            a1  = __hfma2(t01, w2h[4 * q + 1], a1);
            b1v = __hfma2(t11, w2h[4 * q + 1], b1v);
            a2  = __hfma2(t02, w2h[4 * q + 2], a2);
            b2v = __hfma2(t12, w2h[4 * q + 2], b2v);
            a3  = __hfma2(t03, w2h[4 * q + 3], a3);
            b3  = __hfma2(t13, w2h[4 * q + 3], b3);
        }

        // Lean epilogue per i: 3 HADD2 + 1 HADD + 1 cvt + MUFU + FFMA + STG.
        __half2 sa = __hadd2(__hadd2(a0, a1), __hadd2(a2, a3));
        __half2 sb = __hadd2(__hadd2(b0, b1v), __hadd2(b2v, b3));
        float hla = __half2float(__hadd(__low2half(sa), __high2half(sa)));
        float hlb = __half2float(__hadd(__low2half(sb), __high2half(sb)));

        outp[(size_t)ii * NN]       = fmaf(0.5f, tanhf_approx(hla), 0.5f);
        outp[(size_t)(ii + 1) * NN] = fmaf(0.5f, tanhf_approx(hlb), 0.5f);
    }
}

// ---------------------------------------------------------------------------
// Launch: two graph-capturable kernel launches, no allocations, no syncs.
// Inputs (metadata order): X, W1, b1, W2, b2. Output: float32 [4,1024,1024].
// ---------------------------------------------------------------------------
extern "C" void kernel_launch(void* const* d_in, const int* in_sizes, int n_in,
                              void* d_out, int out_size)
{
    const float* X  = (const float*)d_in[0];
    const float* W1 = (const float*)d_in[1];
    const float* b1 = (const float*)d_in[2];
    const float* W2 = (const float*)d_in[3];
    const float* b2 = (const float*)d_in[4];
    float* out = (float*)d_out;

    prep_kernel<<<ROWS / 8, 256>>>(X, W1, b1, W2, b2);

    dim3 grid(NN / JT, NN / I_CHUNK, BB);   // (8, 32, 4) = 1024 blocks, 1 wave
    pair_kernel<<<grid, JT>>>(out);
}